// round 3
// baseline (speedup 1.0000x reference)
#include <cuda_runtime.h>

// Problem constants (fixed by the dataset)
#define NN   4096
#define FDIM 256
#define BB   8
#define WPR  (NN / 32)          // 128 bitmask words per adjacency row
#define MAXD 128                // neighbor-list slab stride (P[deg>128] ~ 1e-40)

// -------- scratch (static __device__ arrays; no allocation allowed) --------
__device__ unsigned g_adj[NN * WPR];                    // 2 MB adjacency bitmask (dedup)
__device__ int      g_deg[NN];                          // dedup'd out-degree / cursor
__device__ int      g_nbr[NN * MAXD];                   // 2 MB compacted neighbor lists
__device__ float    g_xt[(size_t)BB * NN * FDIM];       // 32 MB transformed features

// ---------------------------------------------------------------------------
// packed f32x2 helpers (FFMA2 is only reachable via PTX fma.rn.f32x2)
// ---------------------------------------------------------------------------
__device__ __forceinline__ void fma2(unsigned long long& d,
                                     unsigned long long a,
                                     unsigned long long b) {
    asm("fma.rn.f32x2 %0, %1, %2, %0;" : "+l"(d) : "l"(a), "l"(b));
}
__device__ __forceinline__ unsigned long long dup2(float x) {
    unsigned long long r;
    asm("mov.b64 %0, {%1, %1};" : "=l"(r) : "f"(x));
    return r;
}

// ---------------------------------------------------------------------------
// Kernel 1: zero bitmask + degree
// ---------------------------------------------------------------------------
__global__ void k_zero() {
    int i = blockIdx.x * blockDim.x + threadIdx.x;
    if (i < NN * WPR) g_adj[i] = 0u;
    if (i < NN)       g_deg[i] = 0;
}

// ---------------------------------------------------------------------------
// Kernel 2: build dedup'd neighbor lists.
// ---------------------------------------------------------------------------
__global__ void k_edges(const int* __restrict__ ei, int E) {
    int e = blockIdx.x * blockDim.x + threadIdx.x;
    if (e >= E) return;
    int src = ei[e];
    int dst = ei[E + e];
    unsigned mask = 1u << (dst & 31);
    unsigned old = atomicOr(&g_adj[src * WPR + (dst >> 5)], mask);
    if (!(old & mask)) {
        int pos = atomicAdd(&g_deg[src], 1);
        if (pos < MAXD) g_nbr[src * MAXD + pos] = dst;
    }
}

// ---------------------------------------------------------------------------
// Kernel 3: xt = x @ W   (M = B*N = 32768, K = 256, Nout = 256)
// fp32 SGEMM with packed fma.rn.f32x2 inner loop (2 FMAs per issue slot)
// 128x128 block tile, BK=8, 8x8 per-thread micro-tile, 2-stage double buffer.
// Accumulators j-packed: B pairs load directly as 64-bit from smem; epilogue
// stores pairs without unpacking. Only A needs per-k dup (8 mov.b64).
// ---------------------------------------------------------------------------
#define BM 128
#define BN 128
#define BK 8
#define APAD 132

__global__ void __launch_bounds__(256, 2)
k_gemm(const float* __restrict__ x, const float* __restrict__ w) {
    __shared__ float As[2][BK][APAD];   // [stage][k][m], padded
    __shared__ float Bs[2][BK][BN];     // [stage][k][n]

    const int tid = threadIdx.x;
    const int m0 = blockIdx.y * BM;
    const int n0 = blockIdx.x * BN;

    const int tm = (tid >> 4) << 3;     // row offset in tile
    const int tn = (tid & 15) << 3;     // col offset in tile

    const int ar = tid >> 1;            // 0..127   A-load row
    const int ac = (tid & 1) << 2;      // 0 or 4   A-load k
    const int bk = tid >> 5;            // 0..7     B-load k
    const int bn = (tid & 31) << 2;     // 0..124   B-load n

    unsigned long long acc2[8][4];
    #pragma unroll
    for (int i = 0; i < 8; i++)
        #pragma unroll
        for (int j = 0; j < 4; j++) acc2[i][j] = 0ULL;   // = {0.f, 0.f}

    // ---- prologue: fill stage 0 ----
    {
        float4 av = *(const float4*)&x[(size_t)(m0 + ar) * FDIM + ac];
        As[0][ac + 0][ar] = av.x;
        As[0][ac + 1][ar] = av.y;
        As[0][ac + 2][ar] = av.z;
        As[0][ac + 3][ar] = av.w;
        *(float4*)&Bs[0][bk][bn] = *(const float4*)&w[(size_t)bk * FDIM + n0 + bn];
    }
    __syncthreads();

    #pragma unroll
    for (int kt = 0; kt < FDIM / BK; kt++) {
        const int cur = kt & 1;
        const int nxt = cur ^ 1;
        const int k0n = (kt + 1) * BK;

        // issue next-stage global loads early
        float4 av, bv;
        if (k0n < FDIM) {
            av = *(const float4*)&x[(size_t)(m0 + ar) * FDIM + k0n + ac];
            bv = *(const float4*)&w[(size_t)(k0n + bk) * FDIM + n0 + bn];
        }

        // compute on current stage
        #pragma unroll
        for (int k = 0; k < BK; k++) {
            const float4* ap = (const float4*)&As[cur][k][tm];
            float4 aA = ap[0], aB = ap[1];
            const unsigned long long* bp =
                (const unsigned long long*)&Bs[cur][k][tn];
            unsigned long long b2[4];
            b2[0] = bp[0]; b2[1] = bp[1]; b2[2] = bp[2]; b2[3] = bp[3];

            unsigned long long a2[8];
            a2[0] = dup2(aA.x); a2[1] = dup2(aA.y);
            a2[2] = dup2(aA.z); a2[3] = dup2(aA.w);
            a2[4] = dup2(aB.x); a2[5] = dup2(aB.y);
            a2[6] = dup2(aB.z); a2[7] = dup2(aB.w);

            #pragma unroll
            for (int i = 0; i < 8; i++)
                #pragma unroll
                for (int j = 0; j < 4; j++)
                    fma2(acc2[i][j], a2[i], b2[j]);
        }

        // store next stage (different buffer -> safe before barrier)
        if (k0n < FDIM) {
            As[nxt][ac + 0][ar] = av.x;
            As[nxt][ac + 1][ar] = av.y;
            As[nxt][ac + 2][ar] = av.z;
            As[nxt][ac + 3][ar] = av.w;
            *(float4*)&Bs[nxt][bk][bn] = bv;
        }
        __syncthreads();
    }

    // ---- epilogue: store packed pairs directly ----
    #pragma unroll
    for (int i = 0; i < 8; i++) {
        unsigned long long* dst =
            (unsigned long long*)&g_xt[(size_t)(m0 + tm + i) * FDIM + n0 + tn];
        dst[0] = acc2[i][0];
        dst[1] = acc2[i][1];
        dst[2] = acc2[i][2];
        dst[3] = acc2[i][3];
    }
}

// ---------------------------------------------------------------------------
// Kernel 4: sparse aggregation over compacted neighbor lists.
// block = src; 256 threads = feature dim; all 8 batches in registers.
// ---------------------------------------------------------------------------
__global__ void __launch_bounds__(256)
k_agg(const float* __restrict__ bias, float* __restrict__ out) {
    const int src = blockIdx.x;    // 0..4095
    const int f   = threadIdx.x;   // 0..255

    __shared__ int snb[MAXD];
    int deg = g_deg[src];
    if (deg > MAXD) deg = MAXD;
    if (f < deg) snb[f] = g_nbr[src * MAXD + f];
    __syncthreads();

    const float inv = 1.0f / ((float)deg + 1e-6f);
    const float bf  = bias[f];

    float acc[BB];
    #pragma unroll
    for (int b = 0; b < BB; b++) acc[b] = 0.f;

    const size_t batch_stride = (size_t)NN * FDIM;

    int i = 0;
    for (; i + 2 <= deg; i += 2) {
        const float* p0 = &g_xt[(size_t)snb[i]     * FDIM + f];
        const float* p1 = &g_xt[(size_t)snb[i + 1] * FDIM + f];
        float v0[BB], v1[BB];
        #pragma unroll
        for (int b = 0; b < BB; b++) v0[b] = p0[b * batch_stride];
        #pragma unroll
        for (int b = 0; b < BB; b++) v1[b] = p1[b * batch_stride];
        #pragma unroll
        for (int b = 0; b < BB; b++) acc[b] += v0[b] + v1[b];
    }
    if (i < deg) {
        const float* p0 = &g_xt[(size_t)snb[i] * FDIM + f];
        #pragma unroll
        for (int b = 0; b < BB; b++) acc[b] += p0[b * batch_stride];
    }

    #pragma unroll
    for (int b = 0; b < BB; b++)
        out[((size_t)b * NN + src) * FDIM + f] = acc[b] * inv + bf;
}

// ---------------------------------------------------------------------------
extern "C" void kernel_launch(void* const* d_in, const int* in_sizes, int n_in,
                              void* d_out, int out_size) {
    const float* x    = (const float*)d_in[0];   // (8, 4096, 256) f32
    const int*   ei   = (const int*)  d_in[1];   // (2, 131072) i32
    const float* w    = (const float*)d_in[2];   // (256, 256) f32
    const float* bias = (const float*)d_in[3];   // (256,) f32
    float* out = (float*)d_out;

    const int E = in_sizes[1] / 2;

    k_zero<<<(NN * WPR + 255) / 256, 256>>>();
    k_edges<<<(E + 255) / 256, 256>>>(ei, E);
    k_gemm<<<dim3(FDIM / BN, (BB * NN) / BM), 256>>>(x, w);
    k_agg<<<NN, 256>>>(bias, out);
}

// round 5
// speedup vs baseline: 1.4802x; 1.4802x over previous
#include <cuda_runtime.h>
#include <cuda_bf16.h>
#include <cstdint>

// Problem constants (fixed by the dataset)
#define NN   4096
#define FDIM 256
#define BB   8
#define MTOT (BB * NN)          // 32768 rows
#define WPR  (NN / 32)
#define MAXD 128

// -------- scratch (static __device__ arrays; no allocation allowed) --------
__device__ unsigned g_adj[NN * WPR];
__device__ int      g_deg[NN];
__device__ int      g_nbr[NN * MAXD];
__device__ __align__(16) float         g_xt[(size_t)MTOT * FDIM];   // 32 MB
__device__ __align__(16) __nv_bfloat16 g_wh[FDIM * FDIM];           // W^T hi [n][k]
__device__ __align__(16) __nv_bfloat16 g_wl[FDIM * FDIM];           // W^T lo [n][k]

// ---------------------------------------------------------------------------
// Kernel 1: zero bitmask + degree
// ---------------------------------------------------------------------------
__global__ void k_zero() {
    int i = blockIdx.x * blockDim.x + threadIdx.x;
    if (i < NN * WPR) g_adj[i] = 0u;
    if (i < NN)       g_deg[i] = 0;
}

// ---------------------------------------------------------------------------
// Kernel 2: build dedup'd neighbor lists
// ---------------------------------------------------------------------------
__global__ void k_edges(const int* __restrict__ ei, int E) {
    int e = blockIdx.x * blockDim.x + threadIdx.x;
    if (e >= E) return;
    int src = ei[e];
    int dst = ei[E + e];
    unsigned mask = 1u << (dst & 31);
    unsigned old = atomicOr(&g_adj[src * WPR + (dst >> 5)], mask);
    if (!(old & mask)) {
        int pos = atomicAdd(&g_deg[src], 1);
        if (pos < MAXD) g_nbr[src * MAXD + pos] = dst;
    }
}

// ---------------------------------------------------------------------------
// Kernel 3: weight prep — transpose + bf16 hi/lo split
// W [k][n] fp32  ->  g_wh/g_wl [n][k] bf16
// ---------------------------------------------------------------------------
__global__ void k_wprep(const float* __restrict__ w) {
    int i = blockIdx.x * blockDim.x + threadIdx.x;
    if (i >= FDIM * FDIM) return;
    int k = i >> 8, n = i & 255;
    float v = w[i];
    __nv_bfloat16 h = __float2bfloat16(v);
    __nv_bfloat16 l = __float2bfloat16(v - __bfloat162float(h));
    g_wh[n * FDIM + k] = h;
    g_wl[n * FDIM + k] = l;
}

// ---------------------------------------------------------------------------
// Kernel 4: xt = x @ W via portable bf16 mma.sync with 3-term split.
// CTA tile M=128 x N=64. B (hi+lo, full K=256) resident in smem;
// A streamed with fused fp32->bf16 hi/lo conversion, double-buffered.
// ---------------------------------------------------------------------------
#define KS    32                 // A stage depth (k)
#define NKT   (FDIM / KS)        // 8 stages
#define ASTR  40                 // A smem row stride in halves (32 + 8 pad)
#define BSTR  264                // B smem row stride in halves (256 + 8 pad)

#define SB_H  0                                  // 64 * 264 * 2 = 33792
#define SB_L  33792
#define SA    67584                              // stage: 2 types * 128*40*2 = 20480
#define SASTG 20480
#define SATYP 10240
#define S_TOT 108544

extern __shared__ char dsm[];

__device__ __forceinline__ uint32_t smem_u32(const void* p) {
    uint32_t a;
    asm("{ .reg .u64 t; cvta.to.shared.u64 t, %1; cvt.u32.u64 %0, t; }"
        : "=r"(a) : "l"(p));
    return a;
}
__device__ __forceinline__ void ldsm_x4(uint32_t* r, uint32_t addr) {
    asm volatile("ldmatrix.sync.aligned.m8n8.x4.shared.b16 {%0,%1,%2,%3}, [%4];"
                 : "=r"(r[0]), "=r"(r[1]), "=r"(r[2]), "=r"(r[3]) : "r"(addr));
}
__device__ __forceinline__ void ldsm_x2(uint32_t* r, uint32_t addr) {
    asm volatile("ldmatrix.sync.aligned.m8n8.x2.shared.b16 {%0,%1}, [%2];"
                 : "=r"(r[0]), "=r"(r[1]) : "r"(addr));
}
__device__ __forceinline__ void mma_bf16(float* c, const uint32_t* a,
                                         const uint32_t* b) {
    asm volatile(
        "mma.sync.aligned.m16n8k16.row.col.f32.bf16.bf16.f32 "
        "{%0,%1,%2,%3}, {%4,%5,%6,%7}, {%8,%9}, {%0,%1,%2,%3};"
        : "+f"(c[0]), "+f"(c[1]), "+f"(c[2]), "+f"(c[3])
        : "r"(a[0]), "r"(a[1]), "r"(a[2]), "r"(a[3]), "r"(b[0]), "r"(b[1]));
}
__device__ __forceinline__ uint32_t packbf2(float a, float b) {
    __nv_bfloat162 p = __floats2bfloat162_rn(a, b);
    return *(uint32_t*)&p;
}

__global__ void __launch_bounds__(256, 2)
k_gemm_tc(const float* __restrict__ x) {
    const int tid  = threadIdx.x;
    const int lane = tid & 31;
    const int w    = tid >> 5;
    const int wm   = w >> 1;          // 0..3 (32-row block)
    const int wn   = w & 1;           // 0..1 (32-col block)
    const int n0   = blockIdx.x * 64;
    const int m0   = blockIdx.y * 128;
    const uint32_t sb = smem_u32(dsm);

    // ---- preload B (hi + lo, 64 n x 256 k) into smem ----
    {
        #pragma unroll
        for (int q = 0; q < 8; q++) {
            int idx = q * 256 + tid;          // 0..2047
            int n = idx >> 5;                 // 0..63
            int u = idx & 31;                 // uint4 within row
            *(uint4*)(dsm + SB_H + n * (BSTR * 2) + u * 16) =
                *(const uint4*)&g_wh[(size_t)(n0 + n) * FDIM + u * 8];
            *(uint4*)(dsm + SB_L + n * (BSTR * 2) + u * 16) =
                *(const uint4*)&g_wl[(size_t)(n0 + n) * FDIM + u * 8];
        }
    }

    // ---- A staging helpers: row r = tid>>1, kbase = (tid&1)*16 ----
    const int ar = tid >> 1;
    const int akb = (tid & 1) << 4;
    const float4* xrow = (const float4*)&x[(size_t)(m0 + ar) * FDIM + akb];

    // prologue: stage 0
    {
        char* ah = dsm + SA + SATYP * 0 + ar * (ASTR * 2);
        char* al = dsm + SA + SATYP * 1 + ar * (ASTR * 2);
        #pragma unroll
        for (int q = 0; q < 4; q++) {
            float4 f = xrow[q];
            float vv[4] = {f.x, f.y, f.z, f.w};
            uint32_t hp[2], lp[2];
            #pragma unroll
            for (int j = 0; j < 2; j++) {
                float v0 = vv[2 * j], v1 = vv[2 * j + 1];
                __nv_bfloat16 h0 = __float2bfloat16(v0);
                __nv_bfloat16 h1 = __float2bfloat16(v1);
                hp[j] = packbf2(v0, v1);
                lp[j] = packbf2(v0 - __bfloat162float(h0),
                                v1 - __bfloat162float(h1));
            }
            *(uint2*)(ah + (akb + 4 * q) * 2) = make_uint2(hp[0], hp[1]);
            *(uint2*)(al + (akb + 4 * q) * 2) = make_uint2(lp[0], lp[1]);
        }
    }
    __syncthreads();

    float acc[2][4][4];
    #pragma unroll
    for (int i = 0; i < 2; i++)
        #pragma unroll
        for (int j = 0; j < 4; j++)
            #pragma unroll
            for (int r = 0; r < 4; r++) acc[i][j][r] = 0.f;

    for (int kt = 0; kt < NKT; kt++) {
        const int cur = kt & 1;
        const int nxt = cur ^ 1;

        // prefetch next A chunk into registers
        float4 pf[4];
        if (kt + 1 < NKT) {
            const float4* xn = (const float4*)&x[(size_t)(m0 + ar) * FDIM +
                                                 (kt + 1) * KS + akb];
            #pragma unroll
            for (int q = 0; q < 4; q++) pf[q] = xn[q];
        }

        // compute 2 k16 sub-steps from current stage (B resident)
        #pragma unroll
        for (int sub = 0; sub < 2; sub++) {
            const int krel = sub * 16;                  // within A stage
            const int kabs = kt * KS + krel;            // within B resident
            const uint32_t a_base = sb + SA + cur * SASTG;
            const uint32_t arow = (uint32_t)(wm * 32 + (lane & 15)) * (ASTR * 2) +
                                  (uint32_t)(krel + (lane >> 4) * 8) * 2;
            const uint32_t brow = (uint32_t)(wn * 32 + (lane & 7)) * (BSTR * 2) +
                                  (uint32_t)(kabs + ((lane >> 3) & 1) * 8) * 2;

            uint32_t aH[2][4], aL[2][4], bH[4][2], bL[4][2];
            #pragma unroll
            for (int i = 0; i < 2; i++)
                ldsm_x4(aH[i], a_base + SATYP * 0 + arow + i * 16 * (ASTR * 2));
            #pragma unroll
            for (int j = 0; j < 4; j++)
                ldsm_x2(bH[j], sb + SB_H + brow + j * 8 * (BSTR * 2));
            #pragma unroll
            for (int i = 0; i < 2; i++)
                #pragma unroll
                for (int j = 0; j < 4; j++) mma_bf16(acc[i][j], aH[i], bH[j]);

            #pragma unroll
            for (int j = 0; j < 4; j++)
                ldsm_x2(bL[j], sb + SB_L + brow + j * 8 * (BSTR * 2));
            #pragma unroll
            for (int i = 0; i < 2; i++)
                #pragma unroll
                for (int j = 0; j < 4; j++) mma_bf16(acc[i][j], aH[i], bL[j]);

            #pragma unroll
            for (int i = 0; i < 2; i++)
                ldsm_x4(aL[i], a_base + SATYP * 1 + arow + i * 16 * (ASTR * 2));
            #pragma unroll
            for (int i = 0; i < 2; i++)
                #pragma unroll
                for (int j = 0; j < 4; j++) mma_bf16(acc[i][j], aL[i], bH[j]);
        }

        // convert + store next stage
        if (kt + 1 < NKT) {
            char* ah = dsm + SA + nxt * SASTG + SATYP * 0 + ar * (ASTR * 2);
            char* al = dsm + SA + nxt * SASTG + SATYP * 1 + ar * (ASTR * 2);
            #pragma unroll
            for (int q = 0; q < 4; q++) {
                float vv[4] = {pf[q].x, pf[q].y, pf[q].z, pf[q].w};
                uint32_t hp[2], lp[2];
                #pragma unroll
                for (int j = 0; j < 2; j++) {
                    float v0 = vv[2 * j], v1 = vv[2 * j + 1];
                    __nv_bfloat16 h0 = __float2bfloat16(v0);
                    __nv_bfloat16 h1 = __float2bfloat16(v1);
                    hp[j] = packbf2(v0, v1);
                    lp[j] = packbf2(v0 - __bfloat162float(h0),
                                    v1 - __bfloat162float(h1));
                }
                *(uint2*)(ah + (akb + 4 * q) * 2) = make_uint2(hp[0], hp[1]);
                *(uint2*)(al + (akb + 4 * q) * 2) = make_uint2(lp[0], lp[1]);
            }
        }
        __syncthreads();
    }

    // ---- epilogue: D fragment -> g_xt ----
    #pragma unroll
    for (int i = 0; i < 2; i++) {
        #pragma unroll
        for (int j = 0; j < 4; j++) {
            int m = m0 + wm * 32 + i * 16 + (lane >> 2);
            int n = n0 + wn * 32 + j * 8 + (lane & 3) * 2;
            *(float2*)&g_xt[(size_t)m * FDIM + n] =
                make_float2(acc[i][j][0], acc[i][j][1]);
            *(float2*)&g_xt[(size_t)(m + 8) * FDIM + n] =
                make_float2(acc[i][j][2], acc[i][j][3]);
        }
    }
}

// ---------------------------------------------------------------------------
// Kernel 5: sparse aggregation over compacted neighbor lists (unchanged)
// ---------------------------------------------------------------------------
__global__ void __launch_bounds__(256)
k_agg(const float* __restrict__ bias, float* __restrict__ out) {
    const int src = blockIdx.x;
    const int f   = threadIdx.x;

    __shared__ int snb[MAXD];
    int deg = g_deg[src];
    if (deg > MAXD) deg = MAXD;
    if (f < deg) snb[f] = g_nbr[src * MAXD + f];
    __syncthreads();

    const float inv = 1.0f / ((float)deg + 1e-6f);
    const float bf  = bias[f];

    float acc[BB];
    #pragma unroll
    for (int b = 0; b < BB; b++) acc[b] = 0.f;

    const size_t batch_stride = (size_t)NN * FDIM;

    int i = 0;
    for (; i + 2 <= deg; i += 2) {
        const float* p0 = &g_xt[(size_t)snb[i]     * FDIM + f];
        const float* p1 = &g_xt[(size_t)snb[i + 1] * FDIM + f];
        float v0[BB], v1[BB];
        #pragma unroll
        for (int b = 0; b < BB; b++) v0[b] = p0[b * batch_stride];
        #pragma unroll
        for (int b = 0; b < BB; b++) v1[b] = p1[b * batch_stride];
        #pragma unroll
        for (int b = 0; b < BB; b++) acc[b] += v0[b] + v1[b];
    }
    if (i < deg) {
        const float* p0 = &g_xt[(size_t)snb[i] * FDIM + f];
        #pragma unroll
        for (int b = 0; b < BB; b++) acc[b] += p0[b * batch_stride];
    }

    #pragma unroll
    for (int b = 0; b < BB; b++)
        out[((size_t)b * NN + src) * FDIM + f] = acc[b] * inv + bf;
}

// ---------------------------------------------------------------------------
extern "C" void kernel_launch(void* const* d_in, const int* in_sizes, int n_in,
                              void* d_out, int out_size) {
    const float* x    = (const float*)d_in[0];   // (8, 4096, 256) f32
    const int*   ei   = (const int*)  d_in[1];   // (2, 131072) i32
    const float* w    = (const float*)d_in[2];   // (256, 256) f32
    const float* bias = (const float*)d_in[3];   // (256,) f32
    float* out = (float*)d_out;

    const int E = in_sizes[1] / 2;

    cudaFuncSetAttribute(k_gemm_tc, cudaFuncAttributeMaxDynamicSharedMemorySize,
                         S_TOT);

    k_zero<<<(NN * WPR + 255) / 256, 256>>>();
    k_edges<<<(E + 255) / 256, 256>>>(ei, E);
    k_wprep<<<(FDIM * FDIM + 255) / 256, 256>>>(w);
    k_gemm_tc<<<dim3(4, MTOT / 128), 256, S_TOT>>>(x);
    k_agg<<<NN, 256>>>(bias, out);
}